// round 15
// baseline (speedup 1.0000x reference)
#include <cuda_runtime.h>
#include <cuda_fp16.h>
#include <math.h>
#include <stdint.h>

#define N_NODES 100000
#define N_EDGESC 1600000
#define NF 128
#define DIMS 64
#define NC 16
#define NREL 8
#define NP1 640   // layer1 GEMM cols: 512 rel + 64 root + 8 u + 8 v + 48 pad
#define NP2 256   // layer2 GEMM cols: 128 rel + 16 root + 8 u + 8 v + 96 pad
#define AUX1 80   // fp32 aux cols layer1: 64 root + 8 u + 8 v
#define AUX2 32   // fp32 aux cols layer2: 16 root + 8 u + 8 v

#define SCAN_CHUNK 1024
#define SCAN_NBLK 98

// ---- scratch ----
__device__ __half g_m1[(size_t)N_NODES * 512];  // fp16 layer-1 messages
__device__ float  g_a1[(size_t)N_NODES * AUX1]; // fp32 aux: root|u|v
__device__ __half g_m2[(size_t)N_NODES * 128];  // fp16 layer-2 messages
__device__ float  g_a2[(size_t)N_NODES * AUX2];
__device__ float  g_xc[(size_t)N_NODES * NF];   // tf32-rounded x, k-pair packed
__device__ float  g_x2[(size_t)N_NODES * DIMS]; // tf32-rounded layer-1 out, packed
__device__ float  g_W1[NF * NP1];               // tf32 fused weights, pair-row packed
__device__ float  g_W2[DIMS * NP2];
__device__ int    g_rowptr[N_NODES + 1];
__device__ int    g_cnt[N_NODES];
__device__ int    g_bsum[SCAN_NBLK];
__device__ int4   g_edge[N_EDGESC];

__device__ __forceinline__ uint32_t f2tf(float f) {
    uint32_t u;
    asm("cvt.rna.tf32.f32 %0, %1;" : "=r"(u) : "f"(f));
    return u;
}
__device__ __forceinline__ float f2tff(float f) { return __uint_as_float(f2tf(f)); }

__device__ __forceinline__ int POSK(int k) {
    return (k >> 3) * 8 + (k & 3) * 2 + ((k >> 2) & 1);
}

__device__ __forceinline__ void cp16(uint32_t dst, const void* src, int srcsize) {
    asm volatile("cp.async.cg.shared.global [%0], [%1], 16, %2;"
                 :: "r"(dst), "l"(src), "r"(srcsize));
}

__device__ __forceinline__ float lrelu(float e) { return e >= 0.f ? e : 0.2f * e; }

// ---------------------------------------------------------------------------
// Fused prep (unchanged numerics).
// ---------------------------------------------------------------------------
#define NX (N_NODES * NF)
#define NW1 (NF * NP1)
#define NW2 (DIMS * NP2)

__global__ void prepxc_kernel(const float* __restrict__ x,
                              const float* __restrict__ W1, const float* __restrict__ att1,
                              const float* __restrict__ root1,
                              const float* __restrict__ W2, const float* __restrict__ att2,
                              const float* __restrict__ root2) {
    int i = blockIdx.x * blockDim.x + threadIdx.x;
    if (i < NX) {
        int n = i / NF, k = i % NF;
        g_xc[(size_t)n * NF + POSK(k)] = f2tff(x[i]);
        return;
    }
    int j = i - NX;
    if (j < NW1) {
        int f = j / NP1, c = j % NP1;
        float v = 0.f;
        if (c < 512) {
            int r = c >> 6, o = c & 63;
            v = W1[r * NF * DIMS + f * DIMS + o];
        } else if (c < 576) {
            v = root1[f * DIMS + (c - 512)];
        } else if (c < 584) {
            int r = c - 576; float s = 0.f;
            for (int o = 0; o < DIMS; o++) s += W1[r * NF * DIMS + f * DIMS + o] * att1[r * 2 * DIMS + o];
            v = s;
        } else if (c < 592) {
            int r = c - 584; float s = 0.f;
            for (int o = 0; o < DIMS; o++) s += W1[r * NF * DIMS + f * DIMS + o] * att1[r * 2 * DIMS + DIMS + o];
            v = s;
        }
        int prow = (f >> 3) * 4 + (f & 3);
        int sel  = (f >> 2) & 1;
        g_W1[prow * (2 * NP1) + c * 2 + sel] = f2tff(v);
        return;
    }
    int k = j - NW1;
    if (k < NW2) {
        int f = k / NP2, c = k % NP2;
        float v = 0.f;
        if (c < 128) {
            int r = c >> 4, o = c & 15;
            v = W2[r * DIMS * NC + f * NC + o];
        } else if (c < 144) {
            v = root2[f * NC + (c - 128)];
        } else if (c < 152) {
            int r = c - 144; float s = 0.f;
            for (int o = 0; o < NC; o++) s += W2[r * DIMS * NC + f * NC + o] * att2[r * 2 * NC + o];
            v = s;
        } else if (c < 160) {
            int r = c - 152; float s = 0.f;
            for (int o = 0; o < NC; o++) s += W2[r * DIMS * NC + f * NC + o] * att2[r * 2 * NC + NC + o];
            v = s;
        }
        int prow = (f >> 3) * 4 + (f & 3);
        int sel  = (f >> 2) & 1;
        g_W2[prow * (2 * NP2) + c * 2 + sel] = f2tff(v);
    }
}

__global__ void zero_kernel() {
    int i = blockIdx.x * blockDim.x + threadIdx.x;
    if (i < N_NODES) g_cnt[i] = 0;
}

__global__ void hist_kernel(const int* __restrict__ ei) {
    int e = blockIdx.x * blockDim.x + threadIdx.x;
    if (e < N_EDGESC) atomicAdd(&g_cnt[ei[N_EDGESC + e]], 1);
}

__global__ __launch_bounds__(256) void blocksum_kernel() {
    __shared__ int sh[256];
    int b = blockIdx.x, t = threadIdx.x;
    int base = b * SCAN_CHUNK + t * 4;
    int s = 0;
#pragma unroll
    for (int q = 0; q < 4; q++) {
        int i = base + q;
        if (i < N_NODES) s += g_cnt[i];
    }
    sh[t] = s; __syncthreads();
    for (int off = 128; off > 0; off >>= 1) {
        if (t < off) sh[t] += sh[t + off];
        __syncthreads();
    }
    if (t == 0) g_bsum[b] = sh[0];
}

__global__ void scanb_kernel() {
    __shared__ int sh[128];
    int t = threadIdx.x;
    int v = (t < SCAN_NBLK) ? g_bsum[t] : 0;
    sh[t] = v; __syncthreads();
    for (int off = 1; off < 128; off <<= 1) {
        int x = (t >= off) ? sh[t - off] : 0;
        __syncthreads();
        sh[t] += x;
        __syncthreads();
    }
    if (t < SCAN_NBLK) g_bsum[t] = sh[t] - v;
}

__global__ __launch_bounds__(256) void rowptr_kernel() {
    __shared__ int sh[256];
    int b = blockIdx.x, t = threadIdx.x;
    int base = b * SCAN_CHUNK + t * 4;
    int c[4];
#pragma unroll
    for (int q = 0; q < 4; q++) {
        int i = base + q;
        c[q] = (i < N_NODES) ? g_cnt[i] : 0;
    }
    int tot = c[0] + c[1] + c[2] + c[3];
    sh[t] = tot; __syncthreads();
    for (int off = 1; off < 256; off <<= 1) {
        int x = (t >= off) ? sh[t - off] : 0;
        __syncthreads();
        sh[t] += x;
        __syncthreads();
    }
    int off = g_bsum[b] + sh[t] - tot;
#pragma unroll
    for (int q = 0; q < 4; q++) {
        int i = base + q;
        if (i < N_NODES) {
            g_rowptr[i] = off;
            g_cnt[i] = off;
            off += c[q];
        }
    }
    if (b == 0 && t == 0) g_rowptr[N_NODES] = N_EDGESC;
}

__global__ void scatter_kernel(const int* __restrict__ ei, const float* __restrict__ ew,
                               const int* __restrict__ ec) {
    int e = blockIdx.x * blockDim.x + threadIdx.x;
    if (e >= N_EDGESC) return;
    int d = ei[N_EDGESC + e];
    int p = atomicAdd(&g_cnt[d], 1);
    g_edge[p] = make_int4(ei[e], ec[e], __float_as_int(ew[e]), d);
}

// ---------------------------------------------------------------------------
// TF32 GEMM, cp.async 2-stage pipeline, k-pair packed operands.
// Epilogue: message cols -> fp16; aux cols -> fp32. (unchanged)
// ---------------------------------------------------------------------------
#define ARS 24
#define BRS2 264
#define AST (128 * ARS)
#define BST (8 * BRS2)

template <int LAYER>
__global__ __launch_bounds__(256, 2) void gemm_tf32() {
    constexpr int K = (LAYER == 1) ? NF : DIMS;
    constexpr int N = (LAYER == 1) ? NP1 : NP2;
    constexpr int T = K / 16;
    constexpr int MSGC = (LAYER == 1) ? 512 : 128;
    constexpr int AUXC = (LAYER == 1) ? AUX1 : AUX2;
    const float* __restrict__ A  = (LAYER == 1) ? g_xc : g_x2;
    const float* __restrict__ Bw = (LAYER == 1) ? g_W1 : g_W2;
    __half* __restrict__ M       = (LAYER == 1) ? g_m1 : g_m2;
    float* __restrict__ Xa       = (LAYER == 1) ? g_a1 : g_a2;

    __shared__ uint32_t As[2 * AST];
    __shared__ uint32_t Bs[2 * BST];

    int tid = threadIdx.x;
    int lane = tid & 31, wid = tid >> 5;
    int row0 = blockIdx.y * 128, col0 = blockIdx.x * 128;
    int wm = wid >> 2, wn = wid & 3;
    int gq = lane >> 2, tq = lane & 3;

    int ar[2], ac4[2], bprow[2], bcp[2];
#pragma unroll
    for (int p = 0; p < 2; p++) {
        int f = tid + p * 256;
        ar[p] = f >> 2;  ac4[p] = f & 3;
        bprow[p] = f >> 6;  bcp[p] = f & 63;
    }
    uint32_t as_base = (uint32_t)__cvta_generic_to_shared(As);
    uint32_t bs_base = (uint32_t)__cvta_generic_to_shared(Bs);
    uint32_t adst[2], bdst[2];
    const float* asrc[2];
    const float* bsrc[2];
    int asz[2];
#pragma unroll
    for (int p = 0; p < 2; p++) {
        adst[p] = as_base + (uint32_t)(ar[p] * ARS + ac4[p] * 4) * 4u;
        bdst[p] = bs_base + (uint32_t)(bprow[p] * BRS2 + bcp[p] * 4) * 4u;
        int gr = row0 + ar[p];
        asz[p] = (gr < N_NODES) ? 16 : 0;
        int grc = (gr < N_NODES) ? gr : (N_NODES - 1);
        asrc[p] = &A[(size_t)grc * K + ac4[p] * 4];
        bsrc[p] = &Bw[(size_t)bprow[p] * (2 * N) + col0 * 2 + bcp[p] * 4];
    }

#define ISSUE(t, s)                                                            \
    {                                                                          \
        _Pragma("unroll")                                                      \
        for (int p = 0; p < 2; p++) {                                          \
            cp16(adst[p] + (s) * (AST * 4), asrc[p] + (t) * 16, asz[p]);       \
            cp16(bdst[p] + (s) * (BST * 4), bsrc[p] + (size_t)(t) * 16 * N, 16); \
        }                                                                      \
        asm volatile("cp.async.commit_group;" ::: "memory");                   \
    }

    ISSUE(0, 0);
    if (T > 1) ISSUE(1, 1);

    float c[4][4][4];
#pragma unroll
    for (int a = 0; a < 4; a++)
#pragma unroll
        for (int b = 0; b < 4; b++)
#pragma unroll
            for (int d = 0; d < 4; d++) c[a][b][d] = 0.f;

#pragma unroll
    for (int t = 0; t < T; t++) {
        if (t + 1 < T) asm volatile("cp.async.wait_group 1;" ::: "memory");
        else           asm volatile("cp.async.wait_group 0;" ::: "memory");
        __syncthreads();

        const uint32_t* Ab = &As[(t & 1) * AST];
        const uint32_t* Bb = &Bs[(t & 1) * BST];
#pragma unroll
        for (int k8 = 0; k8 < 16; k8 += 8) {
            uint2 va0[4], va1[4], vb[4];
#pragma unroll
            for (int mi = 0; mi < 4; mi++) {
                int R = wm * 64 + mi * 16;
                va0[mi] = *(const uint2*)&Ab[(R + gq) * ARS + k8 + tq * 2];
                va1[mi] = *(const uint2*)&Ab[(R + gq + 8) * ARS + k8 + tq * 2];
            }
#pragma unroll
            for (int nj = 0; nj < 4; nj++) {
                int Cb = wn * 32 + nj * 8;
                vb[nj] = *(const uint2*)&Bb[((k8 >> 1) + tq) * BRS2 + (Cb + gq) * 2];
            }
#pragma unroll
            for (int mi = 0; mi < 4; mi++)
#pragma unroll
                for (int nj = 0; nj < 4; nj++) {
                    asm volatile(
                        "mma.sync.aligned.m16n8k8.row.col.f32.tf32.tf32.f32 "
                        "{%0,%1,%2,%3}, {%4,%5,%6,%7}, {%8,%9}, {%0,%1,%2,%3};\n"
                        : "+f"(c[mi][nj][0]), "+f"(c[mi][nj][1]),
                          "+f"(c[mi][nj][2]), "+f"(c[mi][nj][3])
                        : "r"(va0[mi].x), "r"(va1[mi].x), "r"(va0[mi].y), "r"(va1[mi].y),
                          "r"(vb[nj].x), "r"(vb[nj].y));
                }
        }
        __syncthreads();
        if (t + 2 < T) ISSUE(t + 2, t & 1);
    }
#undef ISSUE

#pragma unroll
    for (int mi = 0; mi < 4; mi++) {
#pragma unroll
        for (int nj = 0; nj < 4; nj++) {
            int row = row0 + wm * 64 + mi * 16 + gq;
            int col = col0 + wn * 32 + nj * 8 + 2 * tq;
            if (col < MSGC) {
                __half2 h0 = __floats2half2_rn(c[mi][nj][0], c[mi][nj][1]);
                __half2 h1 = __floats2half2_rn(c[mi][nj][2], c[mi][nj][3]);
                if (row < N_NODES)
                    *(__half2*)&M[(size_t)row * MSGC + col] = h0;
                if (row + 8 < N_NODES)
                    *(__half2*)&M[(size_t)(row + 8) * MSGC + col] = h1;
            } else if (col < MSGC + AUXC) {
                int ac = col - MSGC;
                if (row < N_NODES)
                    *(float2*)&Xa[(size_t)row * AUXC + ac] = make_float2(c[mi][nj][0], c[mi][nj][1]);
                if (row + 8 < N_NODES)
                    *(float2*)&Xa[(size_t)(row + 8) * AUXC + ac] = make_float2(c[mi][nj][2], c[mi][nj][3]);
            }
        }
    }
}

// ---------------------------------------------------------------------------
// Edge pass layer 1: warp per dst. Payload pre-gather (1 coalesced int4 load
// per 32 edges) + shfl broadcast; u cached in regs; groups of 4 edges so all
// v/message gathers issue before their FMAs (MLP ~8).
// ---------------------------------------------------------------------------
__global__ __launch_bounds__(256) void edge1_kernel(const float* __restrict__ b1) {
    int w = (blockIdx.x * blockDim.x + threadIdx.x) >> 5;
    int lane = threadIdx.x & 31;
    if (w >= N_NODES) return;
    int rb = g_rowptr[w], re = g_rowptr[w + 1];
    size_t abase = (size_t)w * AUX1;

    float ureg = (lane < NREL) ? g_a1[abase + 64 + lane] : 0.f;

    float acc0 = 0.f, acc1 = 0.f, sum = 0.f;
    int f2 = lane * 2;

    for (int base = rb; base < re; base += 32) {
        int n = re - base; if (n > 32) n = 32;
        int4 pl = make_int4(0, 0, 0, 0);
        if (lane < n) pl = g_edge[base + lane];

        for (int j = 0; j < n; j += 4) {
            float uq[4], vq[4], wq[4];
            float2 hq[4];
#pragma unroll
            for (int q = 0; q < 4; q++) {
                int jj = j + q;
                int idx = jj & 31;
                int src = __shfl_sync(0xffffffffu, pl.x, idx);
                int et  = __shfl_sync(0xffffffffu, pl.y, idx);
                wq[q]   = __int_as_float(__shfl_sync(0xffffffffu, pl.z, idx));
                uq[q]   = __shfl_sync(0xffffffffu, ureg, et);
                bool val = jj < n;
                vq[q] = val ? g_a1[(size_t)src * AUX1 + 72 + et] : 0.f;
                hq[q] = val ? __half22float2(*(const __half2*)&g_m1[(size_t)src * 512 + et * DIMS + f2])
                            : make_float2(0.f, 0.f);
            }
#pragma unroll
            for (int q = 0; q < 4; q++) {
                if (j + q < n) {
                    float ex = __expf(lrelu(uq[q] + vq[q]));
                    sum += ex;
                    float cc = wq[q] * ex;
                    acc0 += cc * hq[q].x;
                    acc1 += cc * hq[q].y;
                }
            }
        }
    }

    float inv = 1.f / (sum + 1e-16f);
    float o0 = acc0 * inv + g_a1[abase + f2]     + b1[f2];
    float o1 = acc1 * inv + g_a1[abase + f2 + 1] + b1[f2 + 1];
    o0 = fmaxf(o0, 0.f);
    o1 = fmaxf(o1, 0.f);
    g_x2[(size_t)w * DIMS + POSK(f2)]     = f2tff(o0);
    g_x2[(size_t)w * DIMS + POSK(f2 + 1)] = f2tff(o1);
}

// ---------------------------------------------------------------------------
// Edge pass layer 2: warp per dst; payload pre-gather + shfl; half-warps take
// alternate edges, 4 per half-warp per group (8 gathers in flight per warp).
// ---------------------------------------------------------------------------
__global__ __launch_bounds__(256) void edge2_kernel(const float* __restrict__ b2,
                                                    float* __restrict__ out,
                                                    int write_logits) {
    int d = (blockIdx.x * blockDim.x + threadIdx.x) >> 5;
    int lane = threadIdx.x & 31;
    if (d >= N_NODES) return;
    int rb = g_rowptr[d], re = g_rowptr[d + 1];
    size_t abase = (size_t)d * AUX2;

    float ureg = (lane < NREL) ? g_a2[abase + 16 + lane] : 0.f;

    int hw = lane >> 4, f = lane & 15;
    float acc = 0.f, sum = 0.f;

    for (int base = rb; base < re; base += 32) {
        int n = re - base; if (n > 32) n = 32;
        int4 pl = make_int4(0, 0, 0, 0);
        if (lane < n) pl = g_edge[base + lane];

        for (int j0 = 0; j0 < n; j0 += 8) {
            float uq[4], vq[4], wq[4], hq[4];
#pragma unroll
            for (int q = 0; q < 4; q++) {
                int jj = j0 + hw + 2 * q;
                int idx = jj & 31;
                int src = __shfl_sync(0xffffffffu, pl.x, idx);
                int et  = __shfl_sync(0xffffffffu, pl.y, idx);
                wq[q]   = __int_as_float(__shfl_sync(0xffffffffu, pl.z, idx));
                uq[q]   = __shfl_sync(0xffffffffu, ureg, et);
                bool val = jj < n;
                vq[q] = val ? g_a2[(size_t)src * AUX2 + 24 + et] : 0.f;
                hq[q] = val ? __half2float(g_m2[(size_t)src * 128 + et * NC + f]) : 0.f;
            }
#pragma unroll
            for (int q = 0; q < 4; q++) {
                if (j0 + hw + 2 * q < n) {
                    float ex = __expf(lrelu(uq[q] + vq[q]));
                    sum += ex;
                    acc += wq[q] * ex * hq[q];
                }
            }
        }
    }

    acc += __shfl_xor_sync(0xffffffffu, acc, 16);
    sum += __shfl_xor_sync(0xffffffffu, sum, 16);

    float logit = acc / (sum + 1e-16f) + g_a2[abase + f] + b2[f];

    float mx = logit;
#pragma unroll
    for (int o = 8; o > 0; o >>= 1) mx = fmaxf(mx, __shfl_xor_sync(0xffffffffu, mx, o));
    float ex = __expf(logit - mx);
    float ss = ex;
#pragma unroll
    for (int o = 8; o > 0; o >>= 1) ss += __shfl_xor_sync(0xffffffffu, ss, o);
    float ls = logit - mx - __logf(ss);

    if (lane < 16) {
        out[(size_t)d * NC + f] = ls;
        if (write_logits) out[(size_t)N_NODES * NC + (size_t)d * NC + f] = logit;
    }
}

// ---------------------------------------------------------------------------
extern "C" void kernel_launch(void* const* d_in, const int* in_sizes, int n_in,
                              void* d_out, int out_size) {
    const float* x     = (const float*)d_in[0];
    const int*   ei    = (const int*)d_in[1];
    const float* ew    = (const float*)d_in[2];
    const int*   ec    = (const int*)d_in[3];
    const float* W1    = (const float*)d_in[4];
    const float* att1  = (const float*)d_in[5];
    const float* root1 = (const float*)d_in[6];
    const float* b1    = (const float*)d_in[7];
    const float* W2    = (const float*)d_in[8];
    const float* att2  = (const float*)d_in[9];
    const float* root2 = (const float*)d_in[10];
    const float* b2    = (const float*)d_in[11];
    float* out = (float*)d_out;
    int write_logits = (out_size >= 2 * N_NODES * NC);

    cudaStream_t s1;
    cudaStreamCreateWithFlags(&s1, cudaStreamNonBlocking);
    cudaEvent_t evFork, evJoin;
    cudaEventCreateWithFlags(&evFork, cudaEventDisableTiming);
    cudaEventCreateWithFlags(&evJoin, cudaEventDisableTiming);

    cudaEventRecord(evFork, 0);
    cudaStreamWaitEvent(s1, evFork, 0);

    // Order: zero(1), hist(2), prepxc(3), gemm1(4) <- profiled slot.
    zero_kernel<<<(N_NODES + 255) / 256, 256, 0, s1>>>();
    hist_kernel<<<(N_EDGESC + 255) / 256, 256, 0, s1>>>(ei);

    prepxc_kernel<<<(NX + NW1 + NW2 + 255) / 256, 256>>>(x, W1, att1, root1, W2, att2, root2);
    {
        dim3 grid(NP1 / 128, (N_NODES + 127) / 128);
        gemm_tf32<1><<<grid, 256>>>();
    }

    blocksum_kernel<<<SCAN_NBLK, 256, 0, s1>>>();
    scanb_kernel<<<1, 128, 0, s1>>>();
    rowptr_kernel<<<SCAN_NBLK, 256, 0, s1>>>();
    scatter_kernel<<<(N_EDGESC + 255) / 256, 256, 0, s1>>>(ei, ew, ec);
    cudaEventRecord(evJoin, s1);

    cudaStreamWaitEvent(0, evJoin, 0);

    edge1_kernel<<<(N_NODES * 32 + 255) / 256, 256>>>(b1);

    {
        dim3 grid(NP2 / 128, (N_NODES + 127) / 128);
        gemm_tf32<2><<<grid, 256>>>();
    }
    edge2_kernel<<<(N_NODES * 32 + 255) / 256, 256>>>(b2, out, write_logits);

    cudaEventDestroy(evFork);
    cudaEventDestroy(evJoin);
    cudaStreamDestroy(s1);
}

// round 16
// speedup vs baseline: 1.1714x; 1.1714x over previous
#include <cuda_runtime.h>
#include <cuda_fp16.h>
#include <math.h>
#include <stdint.h>

#define N_NODES 100000
#define N_EDGESC 1600000
#define NF 128
#define DIMS 64
#define NC 16
#define NREL 8
#define NP1 640   // layer1 GEMM cols: 512 rel + 64 root + 8 u + 8 v + 48 pad
#define NP2 256   // layer2 GEMM cols: 128 rel + 16 root + 8 u + 8 v + 96 pad
#define AUX1 80   // fp32 aux cols layer1: 64 root + 8 u + 8 v
#define AUX2 32   // fp32 aux cols layer2: 16 root + 8 u + 8 v

#define SCAN_CHUNK 1024
#define SCAN_NBLK 98

// ---- scratch ----
__device__ __half g_m1[(size_t)N_NODES * 512];  // fp16 layer-1 messages
__device__ float  g_a1[(size_t)N_NODES * AUX1]; // fp32 aux: root|u|v
__device__ __half g_m2[(size_t)N_NODES * 128];  // fp16 layer-2 messages
__device__ float  g_a2[(size_t)N_NODES * AUX2];
__device__ float  g_xc[(size_t)N_NODES * NF];   // tf32-rounded x, k-pair packed
__device__ float  g_x2[(size_t)N_NODES * DIMS]; // tf32-rounded layer-1 out, packed
__device__ float  g_W1[NF * NP1];               // tf32 fused weights, pair-row packed
__device__ float  g_W2[DIMS * NP2];
__device__ int    g_rowptr[N_NODES + 1];
__device__ int    g_cnt[N_NODES];
__device__ int    g_bsum[SCAN_NBLK];
__device__ int4   g_edge[N_EDGESC];

__device__ __forceinline__ uint32_t f2tf(float f) {
    uint32_t u;
    asm("cvt.rna.tf32.f32 %0, %1;" : "=r"(u) : "f"(f));
    return u;
}
__device__ __forceinline__ float f2tff(float f) { return __uint_as_float(f2tf(f)); }

__device__ __forceinline__ int POSK(int k) {
    return (k >> 3) * 8 + (k & 3) * 2 + ((k >> 2) & 1);
}

__device__ __forceinline__ void cp16(uint32_t dst, const void* src, int srcsize) {
    asm volatile("cp.async.cg.shared.global [%0], [%1], 16, %2;"
                 :: "r"(dst), "l"(src), "r"(srcsize));
}

__device__ __forceinline__ float lrelu(float e) { return e >= 0.f ? e : 0.2f * e; }

// ---------------------------------------------------------------------------
// Fused prep (unchanged numerics).
// ---------------------------------------------------------------------------
#define NX (N_NODES * NF)
#define NW1 (NF * NP1)
#define NW2 (DIMS * NP2)

__global__ void prepxc_kernel(const float* __restrict__ x,
                              const float* __restrict__ W1, const float* __restrict__ att1,
                              const float* __restrict__ root1,
                              const float* __restrict__ W2, const float* __restrict__ att2,
                              const float* __restrict__ root2) {
    int i = blockIdx.x * blockDim.x + threadIdx.x;
    if (i < NX) {
        int n = i / NF, k = i % NF;
        g_xc[(size_t)n * NF + POSK(k)] = f2tff(x[i]);
        return;
    }
    int j = i - NX;
    if (j < NW1) {
        int f = j / NP1, c = j % NP1;
        float v = 0.f;
        if (c < 512) {
            int r = c >> 6, o = c & 63;
            v = W1[r * NF * DIMS + f * DIMS + o];
        } else if (c < 576) {
            v = root1[f * DIMS + (c - 512)];
        } else if (c < 584) {
            int r = c - 576; float s = 0.f;
            for (int o = 0; o < DIMS; o++) s += W1[r * NF * DIMS + f * DIMS + o] * att1[r * 2 * DIMS + o];
            v = s;
        } else if (c < 592) {
            int r = c - 584; float s = 0.f;
            for (int o = 0; o < DIMS; o++) s += W1[r * NF * DIMS + f * DIMS + o] * att1[r * 2 * DIMS + DIMS + o];
            v = s;
        }
        int prow = (f >> 3) * 4 + (f & 3);
        int sel  = (f >> 2) & 1;
        g_W1[prow * (2 * NP1) + c * 2 + sel] = f2tff(v);
        return;
    }
    int k = j - NW1;
    if (k < NW2) {
        int f = k / NP2, c = k % NP2;
        float v = 0.f;
        if (c < 128) {
            int r = c >> 4, o = c & 15;
            v = W2[r * DIMS * NC + f * NC + o];
        } else if (c < 144) {
            v = root2[f * NC + (c - 128)];
        } else if (c < 152) {
            int r = c - 144; float s = 0.f;
            for (int o = 0; o < NC; o++) s += W2[r * DIMS * NC + f * NC + o] * att2[r * 2 * NC + o];
            v = s;
        } else if (c < 160) {
            int r = c - 152; float s = 0.f;
            for (int o = 0; o < NC; o++) s += W2[r * DIMS * NC + f * NC + o] * att2[r * 2 * NC + NC + o];
            v = s;
        }
        int prow = (f >> 3) * 4 + (f & 3);
        int sel  = (f >> 2) & 1;
        g_W2[prow * (2 * NP2) + c * 2 + sel] = f2tff(v);
    }
}

__global__ void zero_kernel() {
    int i = blockIdx.x * blockDim.x + threadIdx.x;
    if (i < N_NODES) g_cnt[i] = 0;
}

__global__ void hist_kernel(const int* __restrict__ ei) {
    int e = blockIdx.x * blockDim.x + threadIdx.x;
    if (e < N_EDGESC) atomicAdd(&g_cnt[ei[N_EDGESC + e]], 1);
}

__global__ __launch_bounds__(256) void blocksum_kernel() {
    __shared__ int sh[256];
    int b = blockIdx.x, t = threadIdx.x;
    int base = b * SCAN_CHUNK + t * 4;
    int s = 0;
#pragma unroll
    for (int q = 0; q < 4; q++) {
        int i = base + q;
        if (i < N_NODES) s += g_cnt[i];
    }
    sh[t] = s; __syncthreads();
    for (int off = 128; off > 0; off >>= 1) {
        if (t < off) sh[t] += sh[t + off];
        __syncthreads();
    }
    if (t == 0) g_bsum[b] = sh[0];
}

__global__ void scanb_kernel() {
    __shared__ int sh[128];
    int t = threadIdx.x;
    int v = (t < SCAN_NBLK) ? g_bsum[t] : 0;
    sh[t] = v; __syncthreads();
    for (int off = 1; off < 128; off <<= 1) {
        int x = (t >= off) ? sh[t - off] : 0;
        __syncthreads();
        sh[t] += x;
        __syncthreads();
    }
    if (t < SCAN_NBLK) g_bsum[t] = sh[t] - v;
}

__global__ __launch_bounds__(256) void rowptr_kernel() {
    __shared__ int sh[256];
    int b = blockIdx.x, t = threadIdx.x;
    int base = b * SCAN_CHUNK + t * 4;
    int c[4];
#pragma unroll
    for (int q = 0; q < 4; q++) {
        int i = base + q;
        c[q] = (i < N_NODES) ? g_cnt[i] : 0;
    }
    int tot = c[0] + c[1] + c[2] + c[3];
    sh[t] = tot; __syncthreads();
    for (int off = 1; off < 256; off <<= 1) {
        int x = (t >= off) ? sh[t - off] : 0;
        __syncthreads();
        sh[t] += x;
        __syncthreads();
    }
    int off = g_bsum[b] + sh[t] - tot;
#pragma unroll
    for (int q = 0; q < 4; q++) {
        int i = base + q;
        if (i < N_NODES) {
            g_rowptr[i] = off;
            g_cnt[i] = off;
            off += c[q];
        }
    }
    if (b == 0 && t == 0) g_rowptr[N_NODES] = N_EDGESC;
}

__global__ void scatter_kernel(const int* __restrict__ ei, const float* __restrict__ ew,
                               const int* __restrict__ ec) {
    int e = blockIdx.x * blockDim.x + threadIdx.x;
    if (e >= N_EDGESC) return;
    int d = ei[N_EDGESC + e];
    int p = atomicAdd(&g_cnt[d], 1);
    g_edge[p] = make_int4(ei[e], ec[e], __float_as_int(ew[e]), d);
}

// ---------------------------------------------------------------------------
// TF32 GEMM, cp.async 2-stage pipeline, k-pair packed operands.
// Epilogue: message cols -> fp16; aux cols -> fp32. (unchanged)
// ---------------------------------------------------------------------------
#define ARS 24
#define BRS2 264
#define AST (128 * ARS)
#define BST (8 * BRS2)

template <int LAYER>
__global__ __launch_bounds__(256, 2) void gemm_tf32() {
    constexpr int K = (LAYER == 1) ? NF : DIMS;
    constexpr int N = (LAYER == 1) ? NP1 : NP2;
    constexpr int T = K / 16;
    constexpr int MSGC = (LAYER == 1) ? 512 : 128;
    constexpr int AUXC = (LAYER == 1) ? AUX1 : AUX2;
    const float* __restrict__ A  = (LAYER == 1) ? g_xc : g_x2;
    const float* __restrict__ Bw = (LAYER == 1) ? g_W1 : g_W2;
    __half* __restrict__ M       = (LAYER == 1) ? g_m1 : g_m2;
    float* __restrict__ Xa       = (LAYER == 1) ? g_a1 : g_a2;

    __shared__ uint32_t As[2 * AST];
    __shared__ uint32_t Bs[2 * BST];

    int tid = threadIdx.x;
    int lane = tid & 31, wid = tid >> 5;
    int row0 = blockIdx.y * 128, col0 = blockIdx.x * 128;
    int wm = wid >> 2, wn = wid & 3;
    int gq = lane >> 2, tq = lane & 3;

    int ar[2], ac4[2], bprow[2], bcp[2];
#pragma unroll
    for (int p = 0; p < 2; p++) {
        int f = tid + p * 256;
        ar[p] = f >> 2;  ac4[p] = f & 3;
        bprow[p] = f >> 6;  bcp[p] = f & 63;
    }
    uint32_t as_base = (uint32_t)__cvta_generic_to_shared(As);
    uint32_t bs_base = (uint32_t)__cvta_generic_to_shared(Bs);
    uint32_t adst[2], bdst[2];
    const float* asrc[2];
    const float* bsrc[2];
    int asz[2];
#pragma unroll
    for (int p = 0; p < 2; p++) {
        adst[p] = as_base + (uint32_t)(ar[p] * ARS + ac4[p] * 4) * 4u;
        bdst[p] = bs_base + (uint32_t)(bprow[p] * BRS2 + bcp[p] * 4) * 4u;
        int gr = row0 + ar[p];
        asz[p] = (gr < N_NODES) ? 16 : 0;
        int grc = (gr < N_NODES) ? gr : (N_NODES - 1);
        asrc[p] = &A[(size_t)grc * K + ac4[p] * 4];
        bsrc[p] = &Bw[(size_t)bprow[p] * (2 * N) + col0 * 2 + bcp[p] * 4];
    }

#define ISSUE(t, s)                                                            \
    {                                                                          \
        _Pragma("unroll")                                                      \
        for (int p = 0; p < 2; p++) {                                          \
            cp16(adst[p] + (s) * (AST * 4), asrc[p] + (t) * 16, asz[p]);       \
            cp16(bdst[p] + (s) * (BST * 4), bsrc[p] + (size_t)(t) * 16 * N, 16); \
        }                                                                      \
        asm volatile("cp.async.commit_group;" ::: "memory");                   \
    }

    ISSUE(0, 0);
    if (T > 1) ISSUE(1, 1);

    float c[4][4][4];
#pragma unroll
    for (int a = 0; a < 4; a++)
#pragma unroll
        for (int b = 0; b < 4; b++)
#pragma unroll
            for (int d = 0; d < 4; d++) c[a][b][d] = 0.f;

#pragma unroll
    for (int t = 0; t < T; t++) {
        if (t + 1 < T) asm volatile("cp.async.wait_group 1;" ::: "memory");
        else           asm volatile("cp.async.wait_group 0;" ::: "memory");
        __syncthreads();

        const uint32_t* Ab = &As[(t & 1) * AST];
        const uint32_t* Bb = &Bs[(t & 1) * BST];
#pragma unroll
        for (int k8 = 0; k8 < 16; k8 += 8) {
            uint2 va0[4], va1[4], vb[4];
#pragma unroll
            for (int mi = 0; mi < 4; mi++) {
                int R = wm * 64 + mi * 16;
                va0[mi] = *(const uint2*)&Ab[(R + gq) * ARS + k8 + tq * 2];
                va1[mi] = *(const uint2*)&Ab[(R + gq + 8) * ARS + k8 + tq * 2];
            }
#pragma unroll
            for (int nj = 0; nj < 4; nj++) {
                int Cb = wn * 32 + nj * 8;
                vb[nj] = *(const uint2*)&Bb[((k8 >> 1) + tq) * BRS2 + (Cb + gq) * 2];
            }
#pragma unroll
            for (int mi = 0; mi < 4; mi++)
#pragma unroll
                for (int nj = 0; nj < 4; nj++) {
                    asm volatile(
                        "mma.sync.aligned.m16n8k8.row.col.f32.tf32.tf32.f32 "
                        "{%0,%1,%2,%3}, {%4,%5,%6,%7}, {%8,%9}, {%0,%1,%2,%3};\n"
                        : "+f"(c[mi][nj][0]), "+f"(c[mi][nj][1]),
                          "+f"(c[mi][nj][2]), "+f"(c[mi][nj][3])
                        : "r"(va0[mi].x), "r"(va1[mi].x), "r"(va0[mi].y), "r"(va1[mi].y),
                          "r"(vb[nj].x), "r"(vb[nj].y));
                }
        }
        __syncthreads();
        if (t + 2 < T) ISSUE(t + 2, t & 1);
    }
#undef ISSUE

#pragma unroll
    for (int mi = 0; mi < 4; mi++) {
#pragma unroll
        for (int nj = 0; nj < 4; nj++) {
            int row = row0 + wm * 64 + mi * 16 + gq;
            int col = col0 + wn * 32 + nj * 8 + 2 * tq;
            if (col < MSGC) {
                __half2 h0 = __floats2half2_rn(c[mi][nj][0], c[mi][nj][1]);
                __half2 h1 = __floats2half2_rn(c[mi][nj][2], c[mi][nj][3]);
                if (row < N_NODES)
                    *(__half2*)&M[(size_t)row * MSGC + col] = h0;
                if (row + 8 < N_NODES)
                    *(__half2*)&M[(size_t)(row + 8) * MSGC + col] = h1;
            } else if (col < MSGC + AUXC) {
                int ac = col - MSGC;
                if (row < N_NODES)
                    *(float2*)&Xa[(size_t)row * AUXC + ac] = make_float2(c[mi][nj][0], c[mi][nj][1]);
                if (row + 8 < N_NODES)
                    *(float2*)&Xa[(size_t)(row + 8) * AUXC + ac] = make_float2(c[mi][nj][2], c[mi][nj][3]);
            }
        }
    }
}

// ---------------------------------------------------------------------------
// Edge pass layer 1: warp per dst, no-max softmax, fp16 message gather,
// fp32 u/v from aux. Round-14 structure, unrolled x4 (4 gathers in flight).
// ---------------------------------------------------------------------------
__global__ __launch_bounds__(256) void edge1_kernel(const float* __restrict__ b1) {
    int w = (blockIdx.x * blockDim.x + threadIdx.x) >> 5;
    int lane = threadIdx.x & 31;
    if (w >= N_NODES) return;
    int rb = g_rowptr[w], re = g_rowptr[w + 1];
    size_t abase = (size_t)w * AUX1;

    float acc0 = 0.f, acc1 = 0.f, sum = 0.f;
    int f2 = lane * 2;
    int i = rb;
    for (; i + 4 <= re; i += 4) {
        int4 pl[4];
        pl[0] = g_edge[i];     pl[1] = g_edge[i + 1];
        pl[2] = g_edge[i + 2]; pl[3] = g_edge[i + 3];
        float uq[4], vq[4];
        float2 hq[4];
#pragma unroll
        for (int q = 0; q < 4; q++) {
            uq[q] = g_a1[abase + 64 + pl[q].y];
            vq[q] = g_a1[(size_t)pl[q].x * AUX1 + 72 + pl[q].y];
            hq[q] = __half22float2(*(const __half2*)&g_m1[(size_t)pl[q].x * 512 + pl[q].y * DIMS + f2]);
        }
#pragma unroll
        for (int q = 0; q < 4; q++) {
            float ex = __expf(lrelu(uq[q] + vq[q]));
            sum += ex;
            float cc = __int_as_float(pl[q].z) * ex;
            acc0 += cc * hq[q].x;
            acc1 += cc * hq[q].y;
        }
    }
    for (; i < re; i++) {
        int4 pl = g_edge[i];
        float u = g_a1[abase + 64 + pl.y];
        float v = g_a1[(size_t)pl.x * AUX1 + 72 + pl.y];
        float2 hv = __half22float2(*(const __half2*)&g_m1[(size_t)pl.x * 512 + pl.y * DIMS + f2]);
        float ex = __expf(lrelu(u + v));
        sum += ex;
        float cc = __int_as_float(pl.z) * ex;
        acc0 += cc * hv.x;
        acc1 += cc * hv.y;
    }
    float inv = 1.f / (sum + 1e-16f);
    float o0 = acc0 * inv + g_a1[abase + f2]     + b1[f2];
    float o1 = acc1 * inv + g_a1[abase + f2 + 1] + b1[f2 + 1];
    o0 = fmaxf(o0, 0.f);
    o1 = fmaxf(o1, 0.f);
    g_x2[(size_t)w * DIMS + POSK(f2)]     = f2tff(o0);
    g_x2[(size_t)w * DIMS + POSK(f2 + 1)] = f2tff(o1);
}

// ---------------------------------------------------------------------------
// Edge pass layer 2: warp per dst, half-warps alternate edges, no-max softmax,
// fp16 messages; round-14 structure unrolled x4; in-warp log_softmax.
// ---------------------------------------------------------------------------
__global__ __launch_bounds__(256) void edge2_kernel(const float* __restrict__ b2,
                                                    float* __restrict__ out,
                                                    int write_logits) {
    int d = (blockIdx.x * blockDim.x + threadIdx.x) >> 5;
    int lane = threadIdx.x & 31;
    if (d >= N_NODES) return;
    int rb = g_rowptr[d], re = g_rowptr[d + 1];
    size_t abase = (size_t)d * AUX2;

    int hw = lane >> 4, f = lane & 15;
    float acc = 0.f, sum = 0.f;
    int i = rb + hw;
    for (; i + 6 < re; i += 8) {
        int4 pl[4];
        pl[0] = g_edge[i];     pl[1] = g_edge[i + 2];
        pl[2] = g_edge[i + 4]; pl[3] = g_edge[i + 6];
        float uq[4], vq[4], hq[4];
#pragma unroll
        for (int q = 0; q < 4; q++) {
            uq[q] = g_a2[abase + 16 + pl[q].y];
            vq[q] = g_a2[(size_t)pl[q].x * AUX2 + 24 + pl[q].y];
            hq[q] = __half2float(g_m2[(size_t)pl[q].x * 128 + pl[q].y * NC + f]);
        }
#pragma unroll
        for (int q = 0; q < 4; q++) {
            float ex = __expf(lrelu(uq[q] + vq[q]));
            sum += ex;
            acc += __int_as_float(pl[q].z) * ex * hq[q];
        }
    }
    for (; i < re; i += 2) {
        int4 pl = g_edge[i];
        float u = g_a2[abase + 16 + pl.y];
        float v = g_a2[(size_t)pl.x * AUX2 + 24 + pl.y];
        float ex = __expf(lrelu(u + v));
        sum += ex;
        acc += __int_as_float(pl.z) * ex * __half2float(g_m2[(size_t)pl.x * 128 + pl.y * NC + f]);
    }
    acc += __shfl_xor_sync(0xffffffffu, acc, 16);
    sum += __shfl_xor_sync(0xffffffffu, sum, 16);

    float logit = acc / (sum + 1e-16f) + g_a2[abase + f] + b2[f];

    float mx = logit;
#pragma unroll
    for (int o = 8; o > 0; o >>= 1) mx = fmaxf(mx, __shfl_xor_sync(0xffffffffu, mx, o));
    float ex = __expf(logit - mx);
    float ss = ex;
#pragma unroll
    for (int o = 8; o > 0; o >>= 1) ss += __shfl_xor_sync(0xffffffffu, ss, o);
    float ls = logit - mx - __logf(ss);

    if (lane < 16) {
        out[(size_t)d * NC + f] = ls;
        if (write_logits) out[(size_t)N_NODES * NC + (size_t)d * NC + f] = logit;
    }
}

// ---------------------------------------------------------------------------
extern "C" void kernel_launch(void* const* d_in, const int* in_sizes, int n_in,
                              void* d_out, int out_size) {
    const float* x     = (const float*)d_in[0];
    const int*   ei    = (const int*)d_in[1];
    const float* ew    = (const float*)d_in[2];
    const int*   ec    = (const int*)d_in[3];
    const float* W1    = (const float*)d_in[4];
    const float* att1  = (const float*)d_in[5];
    const float* root1 = (const float*)d_in[6];
    const float* b1    = (const float*)d_in[7];
    const float* W2    = (const float*)d_in[8];
    const float* att2  = (const float*)d_in[9];
    const float* root2 = (const float*)d_in[10];
    const float* b2    = (const float*)d_in[11];
    float* out = (float*)d_out;
    int write_logits = (out_size >= 2 * N_NODES * NC);

    cudaStream_t s1;
    cudaStreamCreateWithFlags(&s1, cudaStreamNonBlocking);
    cudaEvent_t evFork, evJoin;
    cudaEventCreateWithFlags(&evFork, cudaEventDisableTiming);
    cudaEventCreateWithFlags(&evJoin, cudaEventDisableTiming);

    cudaEventRecord(evFork, 0);
    cudaStreamWaitEvent(s1, evFork, 0);

    // Order: zero(1), hist(2), prepxc(3), gemm1(4) <- profiled slot.
    zero_kernel<<<(N_NODES + 255) / 256, 256, 0, s1>>>();
    hist_kernel<<<(N_EDGESC + 255) / 256, 256, 0, s1>>>(ei);

    prepxc_kernel<<<(NX + NW1 + NW2 + 255) / 256, 256>>>(x, W1, att1, root1, W2, att2, root2);
    {
        dim3 grid(NP1 / 128, (N_NODES + 127) / 128);
        gemm_tf32<1><<<grid, 256>>>();
    }

    blocksum_kernel<<<SCAN_NBLK, 256, 0, s1>>>();
    scanb_kernel<<<1, 128, 0, s1>>>();
    rowptr_kernel<<<SCAN_NBLK, 256, 0, s1>>>();
    scatter_kernel<<<(N_EDGESC + 255) / 256, 256, 0, s1>>>(ei, ew, ec);
    cudaEventRecord(evJoin, s1);

    cudaStreamWaitEvent(0, evJoin, 0);

    edge1_kernel<<<(N_NODES * 32 + 255) / 256, 256>>>(b1);

    {
        dim3 grid(NP2 / 128, (N_NODES + 127) / 128);
        gemm_tf32<2><<<grid, 256>>>();
    }
    edge2_kernel<<<(N_NODES * 32 + 255) / 256, 256>>>(b2, out, write_logits);

    cudaEventDestroy(evFork);
    cudaEventDestroy(evJoin);
    cudaStreamDestroy(s1);
}

// round 17
// speedup vs baseline: 1.3152x; 1.1228x over previous
#include <cuda_runtime.h>
#include <cuda_fp16.h>
#include <math.h>
#include <stdint.h>

#define N_NODES 100000
#define N_EDGESC 1600000
#define NF 128
#define DIMS 64
#define NC 16
#define NREL 8
#define NP1 640   // layer1 GEMM cols: 512 rel + 64 root + 8 u + 8 v + 48 pad
#define NP2 256   // layer2 GEMM cols: 128 rel + 16 root + 8 u + 8 v + 96 pad
#define AUX1 80   // fp32 aux cols layer1: 64 root + 8 u + 8 v
#define AUX2 32   // fp32 aux cols layer2: 16 root + 8 u + 8 v

#define SCAN_CHUNK 1024
#define SCAN_NBLK 98

// ---- scratch ----
__device__ __half g_m1[(size_t)N_NODES * 512];  // fp16 layer-1 messages
__device__ float  g_a1[(size_t)N_NODES * AUX1]; // fp32 aux: root|u|v
__device__ __half g_m2[(size_t)N_NODES * 128];  // fp16 layer-2 messages
__device__ float  g_a2[(size_t)N_NODES * AUX2];
__device__ __half g_xch[(size_t)N_NODES * NF];  // fp16 x, mma-packed
__device__ __half g_x2h[(size_t)N_NODES * DIMS];// fp16 layer-1 out, mma-packed
__device__ __half g_W1h[NF * NP1];              // fp16 fused weights, unit-packed
__device__ __half g_W2h[DIMS * NP2];
__device__ int    g_rowptr[N_NODES + 1];
__device__ int    g_cnt[N_NODES];
__device__ int    g_bsum[SCAN_NBLK];
__device__ int4   g_edge[N_EDGESC];

// A-side packing within a 16-k tile: k -> tile*16 + posu(k2)*2 + (k&1),
// posu(k2) = (k2&3)*2 + (k2>>2), k2 = (k&15)>>1. Makes lane tq's pair
// (k2=tq, k2=tq+4) adjacent -> one LDS.64 per fragment half.
__device__ __forceinline__ int packA(int k) {
    int k2 = (k & 15) >> 1;
    int posu = (k2 & 3) * 2 + (k2 >> 2);
    return (k >> 4) * 16 + posu * 2 + (k & 1);
}

__device__ __forceinline__ void cp16(uint32_t dst, const void* src, int srcsize) {
    asm volatile("cp.async.cg.shared.global [%0], [%1], 16, %2;"
                 :: "r"(dst), "l"(src), "r"(srcsize));
}

__device__ __forceinline__ float lrelu(float e) { return e >= 0.f ? e : 0.2f * e; }

// ---------------------------------------------------------------------------
// Fused prep: fp16-pack x -> g_xch; fused weights -> g_W1h/g_W2h in the
// B-fragment unit layout: half idx = ((t*4+tq)*N + c)*4 + sel*2 + hi,
// where f = 16t + (k2*2+hi), tq = k2&3, sel = k2>>2.
// ---------------------------------------------------------------------------
#define NX (N_NODES * NF)
#define NW1 (NF * NP1)
#define NW2 (DIMS * NP2)

__global__ void prepxc_kernel(const float* __restrict__ x,
                              const float* __restrict__ W1, const float* __restrict__ att1,
                              const float* __restrict__ root1,
                              const float* __restrict__ W2, const float* __restrict__ att2,
                              const float* __restrict__ root2) {
    int i = blockIdx.x * blockDim.x + threadIdx.x;
    if (i < NX) {
        int n = i / NF, k = i % NF;
        g_xch[(size_t)n * NF + packA(k)] = __float2half_rn(x[i]);
        return;
    }
    int j = i - NX;
    if (j < NW1) {
        int f = j / NP1, c = j % NP1;
        float v = 0.f;
        if (c < 512) {
            int r = c >> 6, o = c & 63;
            v = W1[r * NF * DIMS + f * DIMS + o];
        } else if (c < 576) {
            v = root1[f * DIMS + (c - 512)];
        } else if (c < 584) {
            int r = c - 576; float s = 0.f;
            for (int o = 0; o < DIMS; o++) s += W1[r * NF * DIMS + f * DIMS + o] * att1[r * 2 * DIMS + o];
            v = s;
        } else if (c < 592) {
            int r = c - 584; float s = 0.f;
            for (int o = 0; o < DIMS; o++) s += W1[r * NF * DIMS + f * DIMS + o] * att1[r * 2 * DIMS + DIMS + o];
            v = s;
        }
        int t = f >> 4, fi = f & 15;
        int k2 = fi >> 1, hi = fi & 1;
        int tq = k2 & 3, sel = k2 >> 2;
        g_W1h[((size_t)(t * 4 + tq) * NP1 + c) * 4 + sel * 2 + hi] = __float2half_rn(v);
        return;
    }
    int k = j - NW1;
    if (k < NW2) {
        int f = k / NP2, c = k % NP2;
        float v = 0.f;
        if (c < 128) {
            int r = c >> 4, o = c & 15;
            v = W2[r * DIMS * NC + f * NC + o];
        } else if (c < 144) {
            v = root2[f * NC + (c - 128)];
        } else if (c < 152) {
            int r = c - 144; float s = 0.f;
            for (int o = 0; o < NC; o++) s += W2[r * DIMS * NC + f * NC + o] * att2[r * 2 * NC + o];
            v = s;
        } else if (c < 160) {
            int r = c - 152; float s = 0.f;
            for (int o = 0; o < NC; o++) s += W2[r * DIMS * NC + f * NC + o] * att2[r * 2 * NC + NC + o];
            v = s;
        }
        int t = f >> 4, fi = f & 15;
        int k2 = fi >> 1, hi = fi & 1;
        int tq = k2 & 3, sel = k2 >> 2;
        g_W2h[((size_t)(t * 4 + tq) * NP2 + c) * 4 + sel * 2 + hi] = __float2half_rn(v);
    }
}

__global__ void zero_kernel() {
    int i = blockIdx.x * blockDim.x + threadIdx.x;
    if (i < N_NODES) g_cnt[i] = 0;
}

__global__ void hist_kernel(const int* __restrict__ ei) {
    int e = blockIdx.x * blockDim.x + threadIdx.x;
    if (e < N_EDGESC) atomicAdd(&g_cnt[ei[N_EDGESC + e]], 1);
}

__global__ __launch_bounds__(256) void blocksum_kernel() {
    __shared__ int sh[256];
    int b = blockIdx.x, t = threadIdx.x;
    int base = b * SCAN_CHUNK + t * 4;
    int s = 0;
#pragma unroll
    for (int q = 0; q < 4; q++) {
        int i = base + q;
        if (i < N_NODES) s += g_cnt[i];
    }
    sh[t] = s; __syncthreads();
    for (int off = 128; off > 0; off >>= 1) {
        if (t < off) sh[t] += sh[t + off];
        __syncthreads();
    }
    if (t == 0) g_bsum[b] = sh[0];
}

__global__ void scanb_kernel() {
    __shared__ int sh[128];
    int t = threadIdx.x;
    int v = (t < SCAN_NBLK) ? g_bsum[t] : 0;
    sh[t] = v; __syncthreads();
    for (int off = 1; off < 128; off <<= 1) {
        int x = (t >= off) ? sh[t - off] : 0;
        __syncthreads();
        sh[t] += x;
        __syncthreads();
    }
    if (t < SCAN_NBLK) g_bsum[t] = sh[t] - v;
}

__global__ __launch_bounds__(256) void rowptr_kernel() {
    __shared__ int sh[256];
    int b = blockIdx.x, t = threadIdx.x;
    int base = b * SCAN_CHUNK + t * 4;
    int c[4];
#pragma unroll
    for (int q = 0; q < 4; q++) {
        int i = base + q;
        c[q] = (i < N_NODES) ? g_cnt[i] : 0;
    }
    int tot = c[0] + c[1] + c[2] + c[3];
    sh[t] = tot; __syncthreads();
    for (int off = 1; off < 256; off <<= 1) {
        int x = (t >= off) ? sh[t - off] : 0;
        __syncthreads();
        sh[t] += x;
        __syncthreads();
    }
    int off = g_bsum[b] + sh[t] - tot;
#pragma unroll
    for (int q = 0; q < 4; q++) {
        int i = base + q;
        if (i < N_NODES) {
            g_rowptr[i] = off;
            g_cnt[i] = off;
            off += c[q];
        }
    }
    if (b == 0 && t == 0) g_rowptr[N_NODES] = N_EDGESC;
}

__global__ void scatter_kernel(const int* __restrict__ ei, const float* __restrict__ ew,
                               const int* __restrict__ ec) {
    int e = blockIdx.x * blockDim.x + threadIdx.x;
    if (e >= N_EDGESC) return;
    int d = ei[N_EDGESC + e];
    int p = atomicAdd(&g_cnt[d], 1);
    g_edge[p] = make_int4(ei[e], ec[e], __float_as_int(ew[e]), d);
}

// ---------------------------------------------------------------------------
// FP16 tensor-core GEMM (m16n8k16, fp32 accum), cp.async 2-stage pipeline.
// Block 128x128, BK=16, 8 warps (2m x 4n), warp tile 64x32.
// A smem: [128 rows][8 words] (packed 16 halfs/row/tile); frag = 2 LDS.64,
//   banks 8*gq + 2*tq + {0,1}: perfect cover per phase.
// B smem: [4 tq-rows][264 words]; frag = 1 LDS.64 at tq*264+(Cb+gq)*2,
//   banks 8*tq + 2*gq + {0,1}: perfect cover per phase.
// Epilogue: message cols -> fp16; aux cols -> fp32.
// ---------------------------------------------------------------------------
#define ASTH 1024   // words per A stage (128*8)
#define BRSH 264
#define BSTH (4 * BRSH)

template <int LAYER>
__global__ __launch_bounds__(256, 2) void gemm_f16() {
    constexpr int K = (LAYER == 1) ? NF : DIMS;
    constexpr int N = (LAYER == 1) ? NP1 : NP2;
    constexpr int T = K / 16;
    constexpr int MSGC = (LAYER == 1) ? 512 : 128;
    constexpr int AUXC = (LAYER == 1) ? AUX1 : AUX2;
    const __half* __restrict__ A  = (LAYER == 1) ? g_xch : g_x2h;
    const __half* __restrict__ Bw = (LAYER == 1) ? g_W1h : g_W2h;
    __half* __restrict__ M        = (LAYER == 1) ? g_m1 : g_m2;
    float* __restrict__ Xa        = (LAYER == 1) ? g_a1 : g_a2;

    __shared__ uint32_t As[2 * ASTH];
    __shared__ uint32_t Bs[2 * BSTH];

    int tid = threadIdx.x;
    int lane = tid & 31, wid = tid >> 5;
    int row0 = blockIdx.y * 128, col0 = blockIdx.x * 128;
    int wm = wid >> 2, wn = wid & 3;
    int gq = lane >> 2, tq = lane & 3;

    // copy slots: A: row ar (0..127), chunk aq (0..1, 8 halfs each)
    //             B: tq-row btq (0..3), 2-col chunk bc2 (0..63)
    int ar = tid >> 1, aq = tid & 1;
    int btq = tid >> 6, bc2 = tid & 63;

    uint32_t as_base = (uint32_t)__cvta_generic_to_shared(As);
    uint32_t bs_base = (uint32_t)__cvta_generic_to_shared(Bs);
    uint32_t adst = as_base + (uint32_t)(ar * 8 + aq * 4) * 4u;
    uint32_t bdst = bs_base + (uint32_t)(btq * BRSH + bc2 * 4) * 4u;
    int gr = row0 + ar;
    int asz = (gr < N_NODES) ? 16 : 0;
    int grc = (gr < N_NODES) ? gr : (N_NODES - 1);
    const __half* asrc = &A[(size_t)grc * K + aq * 8];
    const __half* bsrc = &Bw[((size_t)btq * N + col0 + bc2 * 2) * 4];

#define ISSUE(t, s)                                                            \
    {                                                                          \
        cp16(adst + (s) * (ASTH * 4), asrc + (t) * 16, asz);                   \
        cp16(bdst + (s) * (BSTH * 4), bsrc + (size_t)(t) * 16 * N, 16);        \
        asm volatile("cp.async.commit_group;" ::: "memory");                   \
    }

    ISSUE(0, 0);
    if (T > 1) ISSUE(1, 1);

    float c[4][4][4];
#pragma unroll
    for (int a = 0; a < 4; a++)
#pragma unroll
        for (int b = 0; b < 4; b++)
#pragma unroll
            for (int d = 0; d < 4; d++) c[a][b][d] = 0.f;

#pragma unroll
    for (int t = 0; t < T; t++) {
        if (t + 1 < T) asm volatile("cp.async.wait_group 1;" ::: "memory");
        else           asm volatile("cp.async.wait_group 0;" ::: "memory");
        __syncthreads();

        const uint32_t* Ab = &As[(t & 1) * ASTH];
        const uint32_t* Bb = &Bs[(t & 1) * BSTH];

        uint2 alo[4], ahi[4], vb[4];
#pragma unroll
        for (int mi = 0; mi < 4; mi++) {
            int R = wm * 64 + mi * 16;
            alo[mi] = *(const uint2*)&Ab[(R + gq) * 8 + tq * 2];      // a0, a2
            ahi[mi] = *(const uint2*)&Ab[(R + gq + 8) * 8 + tq * 2];  // a1, a3
        }
#pragma unroll
        for (int nj = 0; nj < 4; nj++) {
            int Cb = wn * 32 + nj * 8;
            vb[nj] = *(const uint2*)&Bb[btq * 0 + tq * BRSH + (Cb + gq) * 2]; // b0, b1
        }
#pragma unroll
        for (int mi = 0; mi < 4; mi++)
#pragma unroll
            for (int nj = 0; nj < 4; nj++) {
                asm volatile(
                    "mma.sync.aligned.m16n8k16.row.col.f32.f16.f16.f32 "
                    "{%0,%1,%2,%3}, {%4,%5,%6,%7}, {%8,%9}, {%0,%1,%2,%3};\n"
                    : "+f"(c[mi][nj][0]), "+f"(c[mi][nj][1]),
                      "+f"(c[mi][nj][2]), "+f"(c[mi][nj][3])
                    : "r"(alo[mi].x), "r"(ahi[mi].x), "r"(alo[mi].y), "r"(ahi[mi].y),
                      "r"(vb[nj].x), "r"(vb[nj].y));
            }
        __syncthreads();
        if (t + 2 < T) ISSUE(t + 2, t & 1);
    }
#undef ISSUE

#pragma unroll
    for (int mi = 0; mi < 4; mi++) {
#pragma unroll
        for (int nj = 0; nj < 4; nj++) {
            int row = row0 + wm * 64 + mi * 16 + gq;
            int col = col0 + wn * 32 + nj * 8 + 2 * tq;
            if (col < MSGC) {
                __half2 h0 = __floats2half2_rn(c[mi][nj][0], c[mi][nj][1]);
                __half2 h1 = __floats2half2_rn(c[mi][nj][2], c[mi][nj][3]);
                if (row < N_NODES)
                    *(__half2*)&M[(size_t)row * MSGC + col] = h0;
                if (row + 8 < N_NODES)
                    *(__half2*)&M[(size_t)(row + 8) * MSGC + col] = h1;
            } else if (col < MSGC + AUXC) {
                int ac = col - MSGC;
                if (row < N_NODES)
                    *(float2*)&Xa[(size_t)row * AUXC + ac] = make_float2(c[mi][nj][0], c[mi][nj][1]);
                if (row + 8 < N_NODES)
                    *(float2*)&Xa[(size_t)(row + 8) * AUXC + ac] = make_float2(c[mi][nj][2], c[mi][nj][3]);
            }
        }
    }
}

// ---------------------------------------------------------------------------
// Edge pass layer 1: warp per dst, no-max softmax, fp16 message gather,
// fp32 u/v from aux; unrolled x4. Writes packed fp16 g_x2h for GEMM2.
// ---------------------------------------------------------------------------
__global__ __launch_bounds__(256) void edge1_kernel(const float* __restrict__ b1) {
    int w = (blockIdx.x * blockDim.x + threadIdx.x) >> 5;
    int lane = threadIdx.x & 31;
    if (w >= N_NODES) return;
    int rb = g_rowptr[w], re = g_rowptr[w + 1];
    size_t abase = (size_t)w * AUX1;

    float acc0 = 0.f, acc1 = 0.f, sum = 0.f;
    int f2 = lane * 2;
    int i = rb;
    for (; i + 4 <= re; i += 4) {
        int4 pl[4];
        pl[0] = g_edge[i];     pl[1] = g_edge[i + 1];
        pl[2] = g_edge[i + 2]; pl[3] = g_edge[i + 3];
        float uq[4], vq[4];
        float2 hq[4];
#pragma unroll
        for (int q = 0; q < 4; q++) {
            uq[q] = g_a1[abase + 64 + pl[q].y];
            vq[q] = g_a1[(size_t)pl[q].x * AUX1 + 72 + pl[q].y];
            hq[q] = __half22float2(*(const __half2*)&g_m1[(size_t)pl[q].x * 512 + pl[q].y * DIMS + f2]);
        }
#pragma unroll
        for (int q = 0; q < 4; q++) {
            float ex = __expf(lrelu(uq[q] + vq[q]));
            sum += ex;
            float cc = __int_as_float(pl[q].z) * ex;
            acc0 += cc * hq[q].x;
            acc1 += cc * hq[q].y;
        }
    }
    for (; i < re; i++) {
        int4 pl = g_edge[i];
        float u = g_a1[abase + 64 + pl.y];
        float v = g_a1[(size_t)pl.x * AUX1 + 72 + pl.y];
        float2 hv = __half22float2(*(const __half2*)&g_m1[(size_t)pl.x * 512 + pl.y * DIMS + f2]);
        float ex = __expf(lrelu(u + v));
        sum += ex;
        float cc = __int_as_float(pl.z) * ex;
        acc0 += cc * hv.x;
        acc1 += cc * hv.y;
    }
    float inv = 1.f / (sum + 1e-16f);
    float o0 = acc0 * inv + g_a1[abase + f2]     + b1[f2];
    float o1 = acc1 * inv + g_a1[abase + f2 + 1] + b1[f2 + 1];
    o0 = fmaxf(o0, 0.f);
    o1 = fmaxf(o1, 0.f);
    // packed fp16 write: f2 even -> (f2, f2+1) share k2, land adjacent
    int t = f2 >> 4;
    int k2 = (f2 & 15) >> 1;
    int posu = (k2 & 3) * 2 + (k2 >> 2);
    *(__half2*)&g_x2h[(size_t)w * DIMS + t * 16 + posu * 2] = __floats2half2_rn(o0, o1);
}

// ---------------------------------------------------------------------------
// Edge pass layer 2: warp per dst, half-warps alternate edges, no-max softmax,
// fp16 messages; unrolled x4; in-warp log_softmax.
// ---------------------------------------------------------------------------
__global__ __launch_bounds__(256) void edge2_kernel(const float* __restrict__ b2,
                                                    float* __restrict__ out,
                                                    int write_logits) {
    int d = (blockIdx.x * blockDim.x + threadIdx.x) >> 5;
    int lane = threadIdx.x & 31;
    if (d >= N_NODES) return;
    int rb = g_rowptr[d], re = g_rowptr[d + 1];
    size_t abase = (size_t)d * AUX2;

    int hw = lane >> 4, f = lane & 15;
    float acc = 0.f, sum = 0.f;
    int i = rb + hw;
    for (; i + 6 < re; i += 8) {
        int4 pl[4];
        pl[0] = g_edge[i];     pl[1] = g_edge[i + 2];
        pl[2] = g_edge[i + 4]; pl[3] = g_edge[i + 6];
        float uq[4], vq[4], hq[4];
#pragma unroll
        for (int q = 0; q < 4; q++) {
            uq[q] = g_a2[abase + 16 + pl[q].y];
            vq[q] = g_a2[(size_t)pl[q].x * AUX2 + 24 + pl[q].y];
            hq[q] = __half2float(g_m2[(size_t)pl[q].x * 128 + pl[q].y * NC + f]);
        }
#pragma unroll
        for (int q = 0; q < 4; q++) {
            float ex = __expf(lrelu(uq[q] + vq[q]));
            sum += ex;
            acc += __int_as_float(pl[q].z) * ex * hq[q];
        }
    }
    for (; i < re; i += 2) {
        int4 pl = g_edge[i];
        float u = g_a2[abase + 16 + pl.y];
        float v = g_a2[(size_t)pl.x * AUX2 + 24 + pl.y];
        float ex = __expf(lrelu(u + v));
        sum += ex;
        acc += __int_as_float(pl.z) * ex * __half2float(g_m2[(size_t)pl.x * 128 + pl.y * NC + f]);
    }
    acc += __shfl_xor_sync(0xffffffffu, acc, 16);
    sum += __shfl_xor_sync(0xffffffffu, sum, 16);

    float logit = acc / (sum + 1e-16f) + g_a2[abase + f] + b2[f];

    float mx = logit;
#pragma unroll
    for (int o = 8; o > 0; o >>= 1) mx = fmaxf(mx, __shfl_xor_sync(0xffffffffu, mx, o));
    float ex = __expf(logit - mx);
    float ss = ex;
#pragma unroll
    for (int o = 8; o > 0; o >>= 1) ss += __shfl_xor_sync(0xffffffffu, ss, o);
    float ls = logit - mx - __logf(ss);

    if (lane < 16) {
        out[(size_t)d * NC + f] = ls;
        if (write_logits) out[(size_t)N_NODES * NC + (size_t)d * NC + f] = logit;
    }
}

// ---------------------------------------------------------------------------
extern "C" void kernel_launch(void* const* d_in, const int* in_sizes, int n_in,
                              void* d_out, int out_size) {
    const float* x     = (const float*)d_in[0];
    const int*   ei    = (const int*)d_in[1];
    const float* ew    = (const float*)d_in[2];
    const int*   ec    = (const int*)d_in[3];
    const float* W1    = (const float*)d_in[4];
    const float* att1  = (const float*)d_in[5];
    const float* root1 = (const float*)d_in[6];
    const float* b1    = (const float*)d_in[7];
    const float* W2    = (const float*)d_in[8];
    const float* att2  = (const float*)d_in[9];
    const float* root2 = (const float*)d_in[10];
    const float* b2    = (const float*)d_in[11];
    float* out = (float*)d_out;
    int write_logits = (out_size >= 2 * N_NODES * NC);

    cudaStream_t s1;
    cudaStreamCreateWithFlags(&s1, cudaStreamNonBlocking);
    cudaEvent_t evFork, evJoin;
    cudaEventCreateWithFlags(&evFork, cudaEventDisableTiming);
    cudaEventCreateWithFlags(&evJoin, cudaEventDisableTiming);

    cudaEventRecord(evFork, 0);
    cudaStreamWaitEvent(s1, evFork, 0);

    // Order: zero(1), hist(2), prepxc(3), gemm1(4) <- profiled slot.
    zero_kernel<<<(N_NODES + 255) / 256, 256, 0, s1>>>();
    hist_kernel<<<(N_EDGESC + 255) / 256, 256, 0, s1>>>(ei);

    prepxc_kernel<<<(NX + NW1 + NW2 + 255) / 256, 256>>>(x, W1, att1, root1, W2, att2, root2);
    {
        dim3 grid(NP1 / 128, (N_NODES + 127) / 128);
        gemm_f16<1><<<grid, 256>>>();
    }

    blocksum_kernel<<<SCAN_NBLK, 256, 0, s1>>>();
    scanb_kernel<<<1, 128, 0, s1>>>();
    rowptr_kernel<<<SCAN_NBLK, 256, 0, s1>>>();
    scatter_kernel<<<(N_EDGESC + 255) / 256, 256, 0, s1>>>(ei, ew, ec);
    cudaEventRecord(evJoin, s1);

    cudaStreamWaitEvent(0, evJoin, 0);

    edge1_kernel<<<(N_NODES * 32 + 255) / 256, 256>>>(b1);

    {
        dim3 grid(NP2 / 128, (N_NODES + 127) / 128);
        gemm_f16<2><<<grid, 256>>>();
    }
    edge2_kernel<<<(N_NODES * 32 + 255) / 256, 256>>>(b2, out, write_logits);

    cudaEventDestroy(evFork);
    cudaEventDestroy(evJoin);
    cudaStreamDestroy(s1);
}